// round 11
// baseline (speedup 1.0000x reference)
#include <cuda_runtime.h>

// ---------------------------------------------------------------------------
// Fused BasicBlockA, round 11 = R8 (best, 174.8us) + two targeted changes:
//  1) __launch_bounds__(128, 5): cap regs at 102 -> 5 blocks/SM (was 4).
//  2) weights stored PRE-DUPLICATED as u64 f32x2 pairs in SMEM: kills the
//     ~42 dup2 MOVs per task (alu pipe ~= fma pipe in R8 profile).
// Everything else identical to R8: 2x2 px/thread, pair-layout u64 tiles,
// odd strides, hs double buffer, one barrier per latent.
// ---------------------------------------------------------------------------

#define L_DIM 16
#define TX 32
#define TY 16
#define NT 128
#define XQ 10        // x pair q = x rel rows (2q-4, 2q-3)
#define PS 9         // h pair p = h rel rows (2p-2, 2p-1)
#define XCOLS 37     // x storage col = rel col + 2, odd pad
#define HCOLS 35     // h storage col = rel col + 1, odd pad
#define NS1 (PS * 17)  // 153 stage-1 tasks

typedef unsigned long long u64;

struct WB2 {
    u64 w[2][L_DIM][3][16];  // [stage][latent][j][slot]  (f32x2, lanes equal)
    u64 b[L_DIM][3];
};
__device__ WB2 g_wb;

__device__ __forceinline__ float softplus_f(float v) {
    return fmaxf(v, 0.f) + log1pf(expf(-fabsf(v)));
}
__device__ __forceinline__ u64 pack2(float lo, float hi) {
    u64 r; asm("mov.b64 %0, {%1, %2};" : "=l"(r) : "f"(lo), "f"(hi)); return r;
}
__device__ __forceinline__ void unpack2(u64 v, float& lo, float& hi) {
    asm("mov.b64 {%0, %1}, %2;" : "=f"(lo), "=f"(hi) : "l"(v));
}
__device__ __forceinline__ u64 fma2(u64 a, u64 b, u64 c) {
    u64 d; asm("fma.rn.f32x2 %0, %1, %2, %3;" : "=l"(d) : "l"(a), "l"(b), "l"(c)); return d;
}
__device__ __forceinline__ u64 cmb(u64 A, u64 B) {   // (A.hi, B.lo)
    float al, ah, bl, bh;
    unpack2(A, al, ah); unpack2(B, bl, bh);
    return pack2(ah, bl);
}

__device__ __host__ __forceinline__ constexpr int goff(int j, int i) {
    constexpr int t[3][3] = {{0, 5, 10}, {0, 4, 9}, {0, 4, 8}};
    return t[j][i];
}

__global__ void prep_kernel(const float* __restrict__ w1, const float* __restrict__ c1,
                            const float* __restrict__ bias1,
                            const float* __restrict__ w2, const float* __restrict__ c2) {
    int t = threadIdx.x;
    if (t >= 2 * L_DIM) return;
    int stage = t >> 4;
    int l = t & 15;
    const float* W = stage ? w2 : w1;
    const float* C = stage ? c2 : c1;
    for (int j = 0; j < 3; j++) {
        u64* dst = g_wb.w[stage][l][j];
        for (int k = 0; k < 16; k++) dst[k] = 0ull;
        for (int i = 0; i < 3; i++) {
            int base = ((l * 3 + i) * 3 + j) * 9;
            int k = goff(j, i);
            dst[k + 0] = pack2(W[base + 0], W[base + 0]);
            dst[k + 1] = pack2(W[base + 1], W[base + 1]);
            dst[k + 2] = pack2(W[base + 2], W[base + 2]);
            dst[k + 3] = pack2(W[base + 3], W[base + 3]);
            if (j <= i) {
                float v = (j == i) ? softplus_f(C[base + 4]) : W[base + 4];
                dst[k + 4] = pack2(v, v);
            }
        }
    }
    if (stage == 0)
        for (int i = 0; i < 3; i++) g_wb.b[l][i] = pack2(bias1[l * 3 + i], bias1[l * 3 + i]);
}

// One j-chunk, one column, weights already lane-duplicated u64.
template <int J>
__device__ __forceinline__ void conv_j(const u64 (&wv)[16], u64 a[3],
                                       u64 s0, u64 s1, u64 s2, u64 s3, u64 s4) {
#pragma unroll
    for (int i = 0; i < 3; i++) {
        const int k = goff(J, i);
        a[i] = fma2(wv[k + 0], s0, a[i]);
        a[i] = fma2(wv[k + 1], s1, a[i]);
        a[i] = fma2(wv[k + 2], s2, a[i]);
        a[i] = fma2(wv[k + 3], s3, a[i]);
        if (J <= i) a[i] = fma2(wv[k + 4], s4, a[i]);
    }
}

__device__ __forceinline__ float elu_f(float v) {
    return (v > 0.f) ? v : (__expf(v) - 1.f);
}

// Two adjacent columns at pair-row p. aA: col cc, aB: col cc+1.
__device__ __forceinline__ void conv2(const u64* __restrict__ wl,
                                      const u64* __restrict__ tile,
                                      int pstride, int chstride, int p, int cc,
                                      u64 aA[3], u64 aB[3]) {
#pragma unroll
    for (int j = 0; j < 3; j++) {
        const u64* tj = tile + j * chstride + p * pstride + cc;
        u64 L0 = tj[0], L1 = tj[1], L2 = tj[2], L3 = tj[3];
        const u64* tm = tj + pstride;
        u64 M0 = tm[0], M1 = tm[1], M2 = tm[2], M3 = tm[3];
        u64 o0 = cmb(L0, M0), o1 = cmb(L1, M1), o2 = cmb(L2, M2), o3 = cmb(L3, M3);
        alignas(16) u64 wv[16];
        {
            const ulonglong2* ws = (const ulonglong2*)(wl + j * 16);
#pragma unroll
            for (int q = 0; q < 8; q++) ((ulonglong2*)wv)[q] = ws[q];
        }
        if (j == 0) { conv_j<0>(wv, aA, o0, o1, o2, M0, M1); conv_j<0>(wv, aB, o1, o2, o3, M1, M2); }
        if (j == 1) { conv_j<1>(wv, aA, o0, o1, o2, M0, M1); conv_j<1>(wv, aB, o1, o2, o3, M1, M2); }
        if (j == 2) { conv_j<2>(wv, aA, o0, o1, o2, M0, M1); conv_j<2>(wv, aB, o1, o2, o3, M1, M2); }
    }
}

__global__ __launch_bounds__(NT, 5)
void fused_kernel(const float* __restrict__ x, const float* __restrict__ res,
                  float* __restrict__ out) {
    __shared__ alignas(16) WB2 swb;
    __shared__ u64 xsE[3][XQ][XCOLS];
    __shared__ u64 hsE[2][3][PS][HCOLS];

    const int tid = threadIdx.x;
    const int b   = blockIdx.z;
    const int gy0 = blockIdx.y * TY;
    const int gx0 = blockIdx.x * TX;

    // ---- weights/bias into SMEM ----
    {
        const u64* src = (const u64*)&g_wb;
        u64* dst = (u64*)&swb;
        const int n = sizeof(WB2) / 8;
        for (int q = tid; q < n; q += NT) dst[q] = src[q];
    }

    // ---- x tile, pair layout ----
    const float* xb = x + (size_t)b * 3 * 128 * 128;
    for (int q = tid; q < 3 * XQ * XCOLS; q += NT) {
        int j  = q / (XQ * XCOLS);
        int r  = (q / XCOLS) % XQ;
        int cc = q % XCOLS;
        int gy = gy0 + 2 * r - 4;
        int gx = gx0 + cc - 2;
        float lo = 0.f, hi = 0.f;
        if ((unsigned)gx < 128u) {
            const float* col = xb + (size_t)j * 128 * 128 + gx;
            if ((unsigned)gy < 128u)       lo = col[(size_t)gy * 128];
            if ((unsigned)(gy + 1) < 128u) hi = col[(size_t)(gy + 1) * 128];
        }
        xsE[j][r][cc] = pack2(lo, hi);
    }
    __syncthreads();

    // ---- stage-1 task decode (latent-invariant) ----
    const int pc0 = tid % 17, ps0 = tid / 17;
    const int hcA0 = 2 * pc0, hcB0 = hcA0 + 1;
    const bool cokA0 = ((unsigned)(gx0 + hcA0 - 1) < 128u);
    const bool cokB0 = ((unsigned)(gx0 + hcB0 - 1) < 128u);
    const bool rlo0  = ((unsigned)(gy0 + 2 * ps0 - 2) < 128u);
    const bool rhi0  = ((unsigned)(gy0 + 2 * ps0 - 1) < 128u);

    const int t1 = tid + NT;
    const bool has1 = (t1 < NS1);              // tid < 25
    const int pc1 = t1 % 17, ps1 = t1 / 17;
    const int hcA1 = 2 * pc1, hcB1 = hcA1 + 1;
    const bool cokA1 = ((unsigned)(gx0 + hcA1 - 1) < 128u);
    const bool cokB1 = ((unsigned)(gx0 + hcB1 - 1) < 128u);
    const bool rlo1  = ((unsigned)(gy0 + 2 * ps1 - 2) < 128u);
    const bool rhi1  = ((unsigned)(gy0 + 2 * ps1 - 1) < 128u);

    const int tcx = tid % 16;           // out col pair
    const int tpy = tid / 16;           // out pair row

    u64 accA[3], accB[3];
    accA[0] = accA[1] = accA[2] = pack2(0.f, 0.f);
    accB[0] = accB[1] = accB[2] = pack2(0.f, 0.f);

    for (int l = 0; l < L_DIM; l++) {
        const int buf = l & 1;
        const u64* w1l = &swb.w[0][l][0][0];
        const u64 bl0 = swb.b[l][0], bl1 = swb.b[l][1], bl2 = swb.b[l][2];

        // ---- stage 1, task 0 ----
        {
            u64 aA[3] = {bl0, bl1, bl2}, aB[3] = {bl0, bl1, bl2};
            conv2(w1l, &xsE[0][0][0], XCOLS, XQ * XCOLS, ps0, hcA0, aA, aB);
#pragma unroll
            for (int i = 0; i < 3; i++) {
                float lo, hi;
                unpack2(aA[i], lo, hi);
                lo = (cokA0 && rlo0) ? elu_f(lo) : 0.f;
                hi = (cokA0 && rhi0) ? elu_f(hi) : 0.f;
                hsE[buf][i][ps0][hcA0] = pack2(lo, hi);
                unpack2(aB[i], lo, hi);
                lo = (cokB0 && rlo0) ? elu_f(lo) : 0.f;
                hi = (cokB0 && rhi0) ? elu_f(hi) : 0.f;
                hsE[buf][i][ps0][hcB0] = pack2(lo, hi);
            }
        }
        // ---- stage 1, task 1 (25 threads) ----
        if (has1) {
            u64 aA[3] = {bl0, bl1, bl2}, aB[3] = {bl0, bl1, bl2};
            conv2(w1l, &xsE[0][0][0], XCOLS, XQ * XCOLS, ps1, hcA1, aA, aB);
#pragma unroll
            for (int i = 0; i < 3; i++) {
                float lo, hi;
                unpack2(aA[i], lo, hi);
                lo = (cokA1 && rlo1) ? elu_f(lo) : 0.f;
                hi = (cokA1 && rhi1) ? elu_f(hi) : 0.f;
                hsE[buf][i][ps1][hcA1] = pack2(lo, hi);
                unpack2(aB[i], lo, hi);
                lo = (cokB1 && rlo1) ? elu_f(lo) : 0.f;
                hi = (cokB1 && rhi1) ? elu_f(hi) : 0.f;
                hsE[buf][i][ps1][hcB1] = pack2(lo, hi);
            }
        }
        __syncthreads();

        // ---- stage 2 ----
        conv2(&swb.w[1][l][0][0], &hsE[buf][0][0][0], HCOLS, PS * HCOLS,
              tpy, 2 * tcx, accA, accB);
        // next latent writes the other hs buffer: no second barrier
    }

    // ---- epilogue: mean + gated residual ----
    const float r = res[0];
    const float g = (r > 0.f) ? r : 0.f;
    const int gy = gy0 + 2 * tpy;
    const int gxA = gx0 + 2 * tcx;
    float* ob = out + (size_t)b * 3 * 128 * 128;
#pragma unroll
    for (int i = 0; i < 3; i++) {
        float lo, hi, xlo, xhi;
        unpack2(accA[i], lo, hi);
        unpack2(xsE[i][tpy + 2][2 * tcx + 2], xlo, xhi);
        ob[(i * 128 + gy) * 128 + gxA]     = lo * (1.f / 16.f) + g * xlo;
        ob[(i * 128 + gy + 1) * 128 + gxA] = hi * (1.f / 16.f) + g * xhi;
        unpack2(accB[i], lo, hi);
        unpack2(xsE[i][tpy + 2][2 * tcx + 3], xlo, xhi);
        ob[(i * 128 + gy) * 128 + gxA + 1]     = lo * (1.f / 16.f) + g * xlo;
        ob[(i * 128 + gy + 1) * 128 + gxA + 1] = hi * (1.f / 16.f) + g * xhi;
    }
}

extern "C" void kernel_launch(void* const* d_in, const int* in_sizes, int n_in,
                              void* d_out, int out_size) {
    const float* x  = (const float*)d_in[0];
    const float* w1 = (const float*)d_in[1];
    const float* c1 = (const float*)d_in[2];
    const float* b1 = (const float*)d_in[3];
    const float* w2 = (const float*)d_in[4];
    const float* c2 = (const float*)d_in[5];
    const float* rs = (const float*)d_in[6];
    (void)in_sizes; (void)n_in; (void)out_size;

    prep_kernel<<<1, 32>>>(w1, c1, b1, w2, c2);

    dim3 grid(128 / TX, 128 / TY, 64);
    fused_kernel<<<grid, NT>>>(x, rs, (float*)d_out);
}

// round 12
// speedup vs baseline: 1.2081x; 1.2081x over previous
#include <cuda_runtime.h>

// ---------------------------------------------------------------------------
// Fused BasicBlockA, round 12 = R11 minus the forced occupancy bound.
// R11 post-mortem: __launch_bounds__(128,5) capped regs at 96 -> spills
// (L2 1.4%->24.8%). The u64 pre-duplicated weights need ~112-128 regs live.
// This round: same code, default reg budget -> no spills, 4 blocks/SM.
//  - 2x2 px/thread (2 cols x 1 vertical f32x2 pair), FFMA2 math.
//  - pair-layout u64 tiles, odd strides (37/35), cmb() for odd rows.
//  - weights PRE-DUPLICATED u64 f32x2 in SMEM -> no dup2 MOVs at all.
//  - hs double buffered: one __syncthreads per latent.
// ---------------------------------------------------------------------------

#define L_DIM 16
#define TX 32
#define TY 16
#define NT 128
#define XQ 10        // x pair q = x rel rows (2q-4, 2q-3)
#define PS 9         // h pair p = h rel rows (2p-2, 2p-1)
#define XCOLS 37     // x storage col = rel col + 2, odd pad
#define HCOLS 35     // h storage col = rel col + 1, odd pad
#define NS1 (PS * 17)  // 153 stage-1 tasks

typedef unsigned long long u64;

struct WB2 {
    u64 w[2][L_DIM][3][16];  // [stage][latent][j][slot]  (f32x2, lanes equal)
    u64 b[L_DIM][3];
};
__device__ WB2 g_wb;

__device__ __forceinline__ float softplus_f(float v) {
    return fmaxf(v, 0.f) + log1pf(expf(-fabsf(v)));
}
__device__ __forceinline__ u64 pack2(float lo, float hi) {
    u64 r; asm("mov.b64 %0, {%1, %2};" : "=l"(r) : "f"(lo), "f"(hi)); return r;
}
__device__ __forceinline__ void unpack2(u64 v, float& lo, float& hi) {
    asm("mov.b64 {%0, %1}, %2;" : "=f"(lo), "=f"(hi) : "l"(v));
}
__device__ __forceinline__ u64 fma2(u64 a, u64 b, u64 c) {
    u64 d; asm("fma.rn.f32x2 %0, %1, %2, %3;" : "=l"(d) : "l"(a), "l"(b), "l"(c)); return d;
}
__device__ __forceinline__ u64 cmb(u64 A, u64 B) {   // (A.hi, B.lo)
    float al, ah, bl, bh;
    unpack2(A, al, ah); unpack2(B, bl, bh);
    return pack2(ah, bl);
}

__device__ __host__ __forceinline__ constexpr int goff(int j, int i) {
    constexpr int t[3][3] = {{0, 5, 10}, {0, 4, 9}, {0, 4, 8}};
    return t[j][i];
}

__global__ void prep_kernel(const float* __restrict__ w1, const float* __restrict__ c1,
                            const float* __restrict__ bias1,
                            const float* __restrict__ w2, const float* __restrict__ c2) {
    int t = threadIdx.x;
    if (t >= 2 * L_DIM) return;
    int stage = t >> 4;
    int l = t & 15;
    const float* W = stage ? w2 : w1;
    const float* C = stage ? c2 : c1;
    for (int j = 0; j < 3; j++) {
        u64* dst = g_wb.w[stage][l][j];
        for (int k = 0; k < 16; k++) dst[k] = 0ull;
        for (int i = 0; i < 3; i++) {
            int base = ((l * 3 + i) * 3 + j) * 9;
            int k = goff(j, i);
            dst[k + 0] = pack2(W[base + 0], W[base + 0]);
            dst[k + 1] = pack2(W[base + 1], W[base + 1]);
            dst[k + 2] = pack2(W[base + 2], W[base + 2]);
            dst[k + 3] = pack2(W[base + 3], W[base + 3]);
            if (j <= i) {
                float v = (j == i) ? softplus_f(C[base + 4]) : W[base + 4];
                dst[k + 4] = pack2(v, v);
            }
        }
    }
    if (stage == 0)
        for (int i = 0; i < 3; i++) g_wb.b[l][i] = pack2(bias1[l * 3 + i], bias1[l * 3 + i]);
}

// One j-chunk, one column, weights already lane-duplicated u64.
template <int J>
__device__ __forceinline__ void conv_j(const u64 (&wv)[16], u64 a[3],
                                       u64 s0, u64 s1, u64 s2, u64 s3, u64 s4) {
#pragma unroll
    for (int i = 0; i < 3; i++) {
        const int k = goff(J, i);
        a[i] = fma2(wv[k + 0], s0, a[i]);
        a[i] = fma2(wv[k + 1], s1, a[i]);
        a[i] = fma2(wv[k + 2], s2, a[i]);
        a[i] = fma2(wv[k + 3], s3, a[i]);
        if (J <= i) a[i] = fma2(wv[k + 4], s4, a[i]);
    }
}

__device__ __forceinline__ float elu_f(float v) {
    return (v > 0.f) ? v : (__expf(v) - 1.f);
}

// Two adjacent columns at pair-row p. aA: col cc, aB: col cc+1.
__device__ __forceinline__ void conv2(const u64* __restrict__ wl,
                                      const u64* __restrict__ tile,
                                      int pstride, int chstride, int p, int cc,
                                      u64 aA[3], u64 aB[3]) {
#pragma unroll
    for (int j = 0; j < 3; j++) {
        const u64* tj = tile + j * chstride + p * pstride + cc;
        u64 L0 = tj[0], L1 = tj[1], L2 = tj[2], L3 = tj[3];
        const u64* tm = tj + pstride;
        u64 M0 = tm[0], M1 = tm[1], M2 = tm[2], M3 = tm[3];
        u64 o0 = cmb(L0, M0), o1 = cmb(L1, M1), o2 = cmb(L2, M2), o3 = cmb(L3, M3);
        alignas(16) u64 wv[16];
        {
            const ulonglong2* ws = (const ulonglong2*)(wl + j * 16);
#pragma unroll
            for (int q = 0; q < 8; q++) ((ulonglong2*)wv)[q] = ws[q];
        }
        if (j == 0) { conv_j<0>(wv, aA, o0, o1, o2, M0, M1); conv_j<0>(wv, aB, o1, o2, o3, M1, M2); }
        if (j == 1) { conv_j<1>(wv, aA, o0, o1, o2, M0, M1); conv_j<1>(wv, aB, o1, o2, o3, M1, M2); }
        if (j == 2) { conv_j<2>(wv, aA, o0, o1, o2, M0, M1); conv_j<2>(wv, aB, o1, o2, o3, M1, M2); }
    }
}

__global__ __launch_bounds__(NT)
void fused_kernel(const float* __restrict__ x, const float* __restrict__ res,
                  float* __restrict__ out) {
    __shared__ alignas(16) WB2 swb;
    __shared__ u64 xsE[3][XQ][XCOLS];
    __shared__ u64 hsE[2][3][PS][HCOLS];

    const int tid = threadIdx.x;
    const int b   = blockIdx.z;
    const int gy0 = blockIdx.y * TY;
    const int gx0 = blockIdx.x * TX;

    // ---- weights/bias into SMEM ----
    {
        const u64* src = (const u64*)&g_wb;
        u64* dst = (u64*)&swb;
        const int n = sizeof(WB2) / 8;
        for (int q = tid; q < n; q += NT) dst[q] = src[q];
    }

    // ---- x tile, pair layout ----
    const float* xb = x + (size_t)b * 3 * 128 * 128;
    for (int q = tid; q < 3 * XQ * XCOLS; q += NT) {
        int j  = q / (XQ * XCOLS);
        int r  = (q / XCOLS) % XQ;
        int cc = q % XCOLS;
        int gy = gy0 + 2 * r - 4;
        int gx = gx0 + cc - 2;
        float lo = 0.f, hi = 0.f;
        if ((unsigned)gx < 128u) {
            const float* col = xb + (size_t)j * 128 * 128 + gx;
            if ((unsigned)gy < 128u)       lo = col[(size_t)gy * 128];
            if ((unsigned)(gy + 1) < 128u) hi = col[(size_t)(gy + 1) * 128];
        }
        xsE[j][r][cc] = pack2(lo, hi);
    }
    __syncthreads();

    // ---- stage-1 task decode (latent-invariant) ----
    const int pc0 = tid % 17, ps0 = tid / 17;
    const int hcA0 = 2 * pc0, hcB0 = hcA0 + 1;
    const bool cokA0 = ((unsigned)(gx0 + hcA0 - 1) < 128u);
    const bool cokB0 = ((unsigned)(gx0 + hcB0 - 1) < 128u);
    const bool rlo0  = ((unsigned)(gy0 + 2 * ps0 - 2) < 128u);
    const bool rhi0  = ((unsigned)(gy0 + 2 * ps0 - 1) < 128u);

    const int t1 = tid + NT;
    const bool has1 = (t1 < NS1);              // tid < 25
    const int pc1 = t1 % 17, ps1 = t1 / 17;
    const int hcA1 = 2 * pc1, hcB1 = hcA1 + 1;
    const bool cokA1 = ((unsigned)(gx0 + hcA1 - 1) < 128u);
    const bool cokB1 = ((unsigned)(gx0 + hcB1 - 1) < 128u);
    const bool rlo1  = ((unsigned)(gy0 + 2 * ps1 - 2) < 128u);
    const bool rhi1  = ((unsigned)(gy0 + 2 * ps1 - 1) < 128u);

    const int tcx = tid % 16;           // out col pair
    const int tpy = tid / 16;           // out pair row

    u64 accA[3], accB[3];
    accA[0] = accA[1] = accA[2] = pack2(0.f, 0.f);
    accB[0] = accB[1] = accB[2] = pack2(0.f, 0.f);

    for (int l = 0; l < L_DIM; l++) {
        const int buf = l & 1;
        const u64* w1l = &swb.w[0][l][0][0];
        const u64 bl0 = swb.b[l][0], bl1 = swb.b[l][1], bl2 = swb.b[l][2];

        // ---- stage 1, task 0 ----
        {
            u64 aA[3] = {bl0, bl1, bl2}, aB[3] = {bl0, bl1, bl2};
            conv2(w1l, &xsE[0][0][0], XCOLS, XQ * XCOLS, ps0, hcA0, aA, aB);
#pragma unroll
            for (int i = 0; i < 3; i++) {
                float lo, hi;
                unpack2(aA[i], lo, hi);
                lo = (cokA0 && rlo0) ? elu_f(lo) : 0.f;
                hi = (cokA0 && rhi0) ? elu_f(hi) : 0.f;
                hsE[buf][i][ps0][hcA0] = pack2(lo, hi);
                unpack2(aB[i], lo, hi);
                lo = (cokB0 && rlo0) ? elu_f(lo) : 0.f;
                hi = (cokB0 && rhi0) ? elu_f(hi) : 0.f;
                hsE[buf][i][ps0][hcB0] = pack2(lo, hi);
            }
        }
        // ---- stage 1, task 1 (25 threads) ----
        if (has1) {
            u64 aA[3] = {bl0, bl1, bl2}, aB[3] = {bl0, bl1, bl2};
            conv2(w1l, &xsE[0][0][0], XCOLS, XQ * XCOLS, ps1, hcA1, aA, aB);
#pragma unroll
            for (int i = 0; i < 3; i++) {
                float lo, hi;
                unpack2(aA[i], lo, hi);
                lo = (cokA1 && rlo1) ? elu_f(lo) : 0.f;
                hi = (cokA1 && rhi1) ? elu_f(hi) : 0.f;
                hsE[buf][i][ps1][hcA1] = pack2(lo, hi);
                unpack2(aB[i], lo, hi);
                lo = (cokB1 && rlo1) ? elu_f(lo) : 0.f;
                hi = (cokB1 && rhi1) ? elu_f(hi) : 0.f;
                hsE[buf][i][ps1][hcB1] = pack2(lo, hi);
            }
        }
        __syncthreads();

        // ---- stage 2 ----
        conv2(&swb.w[1][l][0][0], &hsE[buf][0][0][0], HCOLS, PS * HCOLS,
              tpy, 2 * tcx, accA, accB);
        // next latent writes the other hs buffer: no second barrier
    }

    // ---- epilogue: mean + gated residual ----
    const float r = res[0];
    const float g = (r > 0.f) ? r : 0.f;
    const int gy = gy0 + 2 * tpy;
    const int gxA = gx0 + 2 * tcx;
    float* ob = out + (size_t)b * 3 * 128 * 128;
#pragma unroll
    for (int i = 0; i < 3; i++) {
        float lo, hi, xlo, xhi;
        unpack2(accA[i], lo, hi);
        unpack2(xsE[i][tpy + 2][2 * tcx + 2], xlo, xhi);
        ob[(i * 128 + gy) * 128 + gxA]     = lo * (1.f / 16.f) + g * xlo;
        ob[(i * 128 + gy + 1) * 128 + gxA] = hi * (1.f / 16.f) + g * xhi;
        unpack2(accB[i], lo, hi);
        unpack2(xsE[i][tpy + 2][2 * tcx + 3], xlo, xhi);
        ob[(i * 128 + gy) * 128 + gxA + 1]     = lo * (1.f / 16.f) + g * xlo;
        ob[(i * 128 + gy + 1) * 128 + gxA + 1] = hi * (1.f / 16.f) + g * xhi;
    }
}

extern "C" void kernel_launch(void* const* d_in, const int* in_sizes, int n_in,
                              void* d_out, int out_size) {
    const float* x  = (const float*)d_in[0];
    const float* w1 = (const float*)d_in[1];
    const float* c1 = (const float*)d_in[2];
    const float* b1 = (const float*)d_in[3];
    const float* w2 = (const float*)d_in[4];
    const float* c2 = (const float*)d_in[5];
    const float* rs = (const float*)d_in[6];
    (void)in_sizes; (void)n_in; (void)out_size;

    prep_kernel<<<1, 32>>>(w1, c1, b1, w2, c2);

    dim3 grid(128 / TX, 128 / TY, 64);
    fused_kernel<<<grid, NT>>>(x, rs, (float*)d_out);
}

// round 13
// speedup vs baseline: 1.8380x; 1.5214x over previous
#include <cuda_runtime.h>

// ---------------------------------------------------------------------------
// Fused BasicBlockA, round 13 = R8 + software-pipelined latent loop + NT=160.
//  - Pipeline: s1(0); bar; for l: { s1(l+1) || s2(l); bar }  -> 2 independent
//    conv2's between barriers (2x ILP), serial depth 2 conv2/latent (was 3).
//  - NT=160: 153 stage-1 tasks -> exactly one per thread. s2/epilogue: tid<128.
//  - f32x2 math, pair-layout u64 tiles, odd strides, cmb() for odd rows.
//  - Weights: R8 scheme (float chunks in SMEM, LDS.128 + dup at use).
// ---------------------------------------------------------------------------

#define L_DIM 16
#define TX 32
#define TY 16
#define NT 160
#define XQ 10        // x pair q = x rel rows (2q-4, 2q-3)
#define PS 9         // h pair p = h rel rows (2p-2, 2p-1)
#define XCOLS 37     // x storage col = rel col + 2, odd pad
#define HCOLS 35     // h storage col = rel col + 1, odd pad
#define NS1 (PS * 17)  // 153 stage-1 tasks

typedef unsigned long long u64;

struct WB2 {
    float w[2][L_DIM][3][16];  // [stage][latent][j][chunk16]
    u64   b[L_DIM][3];
};
__device__ WB2 g_wb;

__device__ __forceinline__ float softplus_f(float v) {
    return fmaxf(v, 0.f) + log1pf(expf(-fabsf(v)));
}
__device__ __forceinline__ u64 pack2(float lo, float hi) {
    u64 r; asm("mov.b64 %0, {%1, %2};" : "=l"(r) : "f"(lo), "f"(hi)); return r;
}
__device__ __forceinline__ void unpack2(u64 v, float& lo, float& hi) {
    asm("mov.b64 {%0, %1}, %2;" : "=f"(lo), "=f"(hi) : "l"(v));
}
__device__ __forceinline__ u64 fma2(u64 a, u64 b, u64 c) {
    u64 d; asm("fma.rn.f32x2 %0, %1, %2, %3;" : "=l"(d) : "l"(a), "l"(b), "l"(c)); return d;
}
__device__ __forceinline__ u64 dup2(float f) { return pack2(f, f); }
__device__ __forceinline__ u64 cmb(u64 A, u64 B) {   // (A.hi, B.lo)
    float al, ah, bl, bh;
    unpack2(A, al, ah); unpack2(B, bl, bh);
    return pack2(ah, bl);
}

__device__ __host__ __forceinline__ constexpr int goff(int j, int i) {
    constexpr int t[3][3] = {{0, 5, 10}, {0, 4, 9}, {0, 4, 8}};
    return t[j][i];
}

__global__ void prep_kernel(const float* __restrict__ w1, const float* __restrict__ c1,
                            const float* __restrict__ bias1,
                            const float* __restrict__ w2, const float* __restrict__ c2) {
    int t = threadIdx.x;
    if (t >= 2 * L_DIM) return;
    int stage = t >> 4;
    int l = t & 15;
    const float* W = stage ? w2 : w1;
    const float* C = stage ? c2 : c1;
    for (int j = 0; j < 3; j++) {
        float* dst = g_wb.w[stage][l][j];
        for (int k = 0; k < 16; k++) dst[k] = 0.f;
        for (int i = 0; i < 3; i++) {
            int base = ((l * 3 + i) * 3 + j) * 9;
            int k = goff(j, i);
            dst[k + 0] = W[base + 0];
            dst[k + 1] = W[base + 1];
            dst[k + 2] = W[base + 2];
            dst[k + 3] = W[base + 3];
            if (j <= i)
                dst[k + 4] = (j == i) ? softplus_f(C[base + 4]) : W[base + 4];
        }
    }
    if (stage == 0)
        for (int i = 0; i < 3; i++)
            g_wb.b[l][i] = pack2(bias1[l * 3 + i], bias1[l * 3 + i]);
}

template <int J>
__device__ __forceinline__ void conv_j(const float (&wf)[16], u64 a[3],
                                       u64 s0, u64 s1, u64 s2, u64 s3, u64 s4) {
#pragma unroll
    for (int i = 0; i < 3; i++) {
        const int k = goff(J, i);
        a[i] = fma2(dup2(wf[k + 0]), s0, a[i]);
        a[i] = fma2(dup2(wf[k + 1]), s1, a[i]);
        a[i] = fma2(dup2(wf[k + 2]), s2, a[i]);
        a[i] = fma2(dup2(wf[k + 3]), s3, a[i]);
        if (J <= i) a[i] = fma2(dup2(wf[k + 4]), s4, a[i]);
    }
}

__device__ __forceinline__ float elu_f(float v) {
    return (v > 0.f) ? v : (__expf(v) - 1.f);
}

// Two adjacent columns at pair-row p. aA: col cc, aB: col cc+1.
__device__ __forceinline__ void conv2(const float* __restrict__ wl,
                                      const u64* __restrict__ tile,
                                      int pstride, int chstride, int p, int cc,
                                      u64 aA[3], u64 aB[3]) {
#pragma unroll
    for (int j = 0; j < 3; j++) {
        const u64* tj = tile + j * chstride + p * pstride + cc;
        u64 L0 = tj[0], L1 = tj[1], L2 = tj[2], L3 = tj[3];
        const u64* tm = tj + pstride;
        u64 M0 = tm[0], M1 = tm[1], M2 = tm[2], M3 = tm[3];
        u64 o0 = cmb(L0, M0), o1 = cmb(L1, M1), o2 = cmb(L2, M2), o3 = cmb(L3, M3);
        alignas(16) float wf[16];
        ((float4*)wf)[0] = ((const float4*)(wl + j * 16))[0];
        ((float4*)wf)[1] = ((const float4*)(wl + j * 16))[1];
        ((float4*)wf)[2] = ((const float4*)(wl + j * 16))[2];
        ((float4*)wf)[3] = ((const float4*)(wl + j * 16))[3];
        if (j == 0) { conv_j<0>(wf, aA, o0, o1, o2, M0, M1); conv_j<0>(wf, aB, o1, o2, o3, M1, M2); }
        if (j == 1) { conv_j<1>(wf, aA, o0, o1, o2, M0, M1); conv_j<1>(wf, aB, o1, o2, o3, M1, M2); }
        if (j == 2) { conv_j<2>(wf, aA, o0, o1, o2, M0, M1); conv_j<2>(wf, aB, o1, o2, o3, M1, M2); }
    }
}

__global__ __launch_bounds__(NT, 3)
void fused_kernel(const float* __restrict__ x, const float* __restrict__ res,
                  float* __restrict__ out) {
    __shared__ alignas(16) WB2 swb;
    __shared__ u64 xsE[3][XQ][XCOLS];
    __shared__ u64 hsE[2][3][PS][HCOLS];

    const int tid = threadIdx.x;
    const int b   = blockIdx.z;
    const int gy0 = blockIdx.y * TY;
    const int gx0 = blockIdx.x * TX;

    // ---- weights/bias into SMEM ----
    {
        const u64* src = (const u64*)&g_wb;
        u64* dst = (u64*)&swb;
        const int n = sizeof(WB2) / 8;
        for (int q = tid; q < n; q += NT) dst[q] = src[q];
    }

    // ---- x tile, pair layout ----
    const float* xb = x + (size_t)b * 3 * 128 * 128;
    for (int q = tid; q < 3 * XQ * XCOLS; q += NT) {
        int j  = q / (XQ * XCOLS);
        int r  = (q / XCOLS) % XQ;
        int cc = q % XCOLS;
        int gy = gy0 + 2 * r - 4;
        int gx = gx0 + cc - 2;
        float lo = 0.f, hi = 0.f;
        if ((unsigned)gx < 128u) {
            const float* col = xb + (size_t)j * 128 * 128 + gx;
            if ((unsigned)gy < 128u)       lo = col[(size_t)gy * 128];
            if ((unsigned)(gy + 1) < 128u) hi = col[(size_t)(gy + 1) * 128];
        }
        xsE[j][r][cc] = pack2(lo, hi);
    }
    __syncthreads();

    // ---- stage-1: exactly one task per thread (tid < 153) ----
    const bool sact = (tid < NS1);
    const int ps0 = sact ? tid / 17 : 0;
    const int pc0 = sact ? tid % 17 : 0;
    const int hcA = 2 * pc0, hcB = hcA + 1;
    const bool cokA = ((unsigned)(gx0 + hcA - 1) < 128u);
    const bool cokB = ((unsigned)(gx0 + hcB - 1) < 128u);
    const bool rlo  = ((unsigned)(gy0 + 2 * ps0 - 2) < 128u);
    const bool rhi  = ((unsigned)(gy0 + 2 * ps0 - 1) < 128u);

    // ---- stage-2: tid < 128 ----
    const bool s2act = (tid < 128);
    const int tcx = tid & 15;          // out col pair
    const int tpy = tid >> 4;          // out pair row (0..7 when active)

    u64 accA[3], accB[3];
    accA[0] = accA[1] = accA[2] = pack2(0.f, 0.f);
    accB[0] = accB[1] = accB[2] = pack2(0.f, 0.f);

    // stage-1 worker: compute latent l's h tile into hsE[l&1]
    auto do_s1 = [&](int l) {
        if (!sact) return;
        const int buf = l & 1;
        const float* w1l = &swb.w[0][l][0][0];
        u64 aA[3] = {swb.b[l][0], swb.b[l][1], swb.b[l][2]};
        u64 aB[3] = {aA[0], aA[1], aA[2]};
        conv2(w1l, &xsE[0][0][0], XCOLS, XQ * XCOLS, ps0, hcA, aA, aB);
#pragma unroll
        for (int i = 0; i < 3; i++) {
            float lo, hi;
            unpack2(aA[i], lo, hi);
            lo = (cokA && rlo) ? elu_f(lo) : 0.f;
            hi = (cokA && rhi) ? elu_f(hi) : 0.f;
            hsE[buf][i][ps0][hcA] = pack2(lo, hi);
            unpack2(aB[i], lo, hi);
            lo = (cokB && rlo) ? elu_f(lo) : 0.f;
            hi = (cokB && rhi) ? elu_f(hi) : 0.f;
            hsE[buf][i][ps0][hcB] = pack2(lo, hi);
        }
    };

    // ---- software-pipelined latent loop ----
    do_s1(0);
    __syncthreads();
#pragma unroll 1
    for (int l = 0; l < L_DIM; l++) {
        if (l + 1 < L_DIM) do_s1(l + 1);               // fills hsE[(l+1)&1]
        if (s2act)                                      // reads hsE[l&1]
            conv2(&swb.w[1][l][0][0], &hsE[l & 1][0][0][0], HCOLS, PS * HCOLS,
                  tpy, 2 * tcx, accA, accB);
        __syncthreads();
    }

    // ---- epilogue: mean + gated residual (tid < 128) ----
    if (s2act) {
        const float r = res[0];
        const float g = (r > 0.f) ? r : 0.f;
        const int gy = gy0 + 2 * tpy;
        const int gxA = gx0 + 2 * tcx;
        float* ob = out + (size_t)b * 3 * 128 * 128;
#pragma unroll
        for (int i = 0; i < 3; i++) {
            float lo, hi, xlo, xhi;
            unpack2(accA[i], lo, hi);
            unpack2(xsE[i][tpy + 2][2 * tcx + 2], xlo, xhi);
            ob[(i * 128 + gy) * 128 + gxA]     = lo * (1.f / 16.f) + g * xlo;
            ob[(i * 128 + gy + 1) * 128 + gxA] = hi * (1.f / 16.f) + g * xhi;
            unpack2(accB[i], lo, hi);
            unpack2(xsE[i][tpy + 2][2 * tcx + 3], xlo, xhi);
            ob[(i * 128 + gy) * 128 + gxA + 1]     = lo * (1.f / 16.f) + g * xlo;
            ob[(i * 128 + gy + 1) * 128 + gxA + 1] = hi * (1.f / 16.f) + g * xhi;
        }
    }
}

extern "C" void kernel_launch(void* const* d_in, const int* in_sizes, int n_in,
                              void* d_out, int out_size) {
    const float* x  = (const float*)d_in[0];
    const float* w1 = (const float*)d_in[1];
    const float* c1 = (const float*)d_in[2];
    const float* b1 = (const float*)d_in[3];
    const float* w2 = (const float*)d_in[4];
    const float* c2 = (const float*)d_in[5];
    const float* rs = (const float*)d_in[6];
    (void)in_sizes; (void)n_in; (void)out_size;

    prep_kernel<<<1, 32>>>(w1, c1, b1, w2, c2);

    dim3 grid(128 / TX, 128 / TY, 64);
    fused_kernel<<<grid, NT>>>(x, rs, (float*)d_out);
}

// round 14
// speedup vs baseline: 1.9942x; 1.0850x over previous
#include <cuda_runtime.h>

// ---------------------------------------------------------------------------
// Fused BasicBlockA, round 14 = R13 (143us) + stage-1 traffic cuts:
//  - xsO: odd-parity x tile copy (prologue) -> s1 ky0 taps are direct LDS.64,
//    zero cmb in stage 1, 7 loads/j instead of 8.
//  - s1 even-row words (M0..M2 per j) hoisted to registers (latent-invariant):
//    s1 data loads 24 -> 12 LDS.64 per latent.
//  - __launch_bounds__(160,4): 4 blocks/SM at ~102 regs.
// Pipeline, stage-2, weights scheme unchanged from R13.
// ---------------------------------------------------------------------------

#define L_DIM 16
#define TX 32
#define TY 16
#define NT 160
#define XQ 10        // xsE pair q = x rel rows (2q-4, 2q-3)
#define XO 9         // xsO pair t = x rel rows (2t-3, 2t-2)
#define PS 9         // h pair p = h rel rows (2p-2, 2p-1)
#define XCOLS 37     // x storage col = rel col + 2, odd pad
#define HCOLS 35     // h storage col = rel col + 1, odd pad
#define NS1 (PS * 17)  // 153 stage-1 tasks

typedef unsigned long long u64;

struct WB2 {
    float w[2][L_DIM][3][16];  // [stage][latent][j][chunk16]
    u64   b[L_DIM][3];
};
__device__ WB2 g_wb;

__device__ __forceinline__ float softplus_f(float v) {
    return fmaxf(v, 0.f) + log1pf(expf(-fabsf(v)));
}
__device__ __forceinline__ u64 pack2(float lo, float hi) {
    u64 r; asm("mov.b64 %0, {%1, %2};" : "=l"(r) : "f"(lo), "f"(hi)); return r;
}
__device__ __forceinline__ void unpack2(u64 v, float& lo, float& hi) {
    asm("mov.b64 {%0, %1}, %2;" : "=f"(lo), "=f"(hi) : "l"(v));
}
__device__ __forceinline__ u64 fma2(u64 a, u64 b, u64 c) {
    u64 d; asm("fma.rn.f32x2 %0, %1, %2, %3;" : "=l"(d) : "l"(a), "l"(b), "l"(c)); return d;
}
__device__ __forceinline__ u64 dup2(float f) { return pack2(f, f); }
__device__ __forceinline__ u64 cmb(u64 A, u64 B) {   // (A.hi, B.lo)
    float al, ah, bl, bh;
    unpack2(A, al, ah); unpack2(B, bl, bh);
    return pack2(ah, bl);
}

__device__ __host__ __forceinline__ constexpr int goff(int j, int i) {
    constexpr int t[3][3] = {{0, 5, 10}, {0, 4, 9}, {0, 4, 8}};
    return t[j][i];
}

__global__ void prep_kernel(const float* __restrict__ w1, const float* __restrict__ c1,
                            const float* __restrict__ bias1,
                            const float* __restrict__ w2, const float* __restrict__ c2) {
    int t = threadIdx.x;
    if (t >= 2 * L_DIM) return;
    int stage = t >> 4;
    int l = t & 15;
    const float* W = stage ? w2 : w1;
    const float* C = stage ? c2 : c1;
    for (int j = 0; j < 3; j++) {
        float* dst = g_wb.w[stage][l][j];
        for (int k = 0; k < 16; k++) dst[k] = 0.f;
        for (int i = 0; i < 3; i++) {
            int base = ((l * 3 + i) * 3 + j) * 9;
            int k = goff(j, i);
            dst[k + 0] = W[base + 0];
            dst[k + 1] = W[base + 1];
            dst[k + 2] = W[base + 2];
            dst[k + 3] = W[base + 3];
            if (j <= i)
                dst[k + 4] = (j == i) ? softplus_f(C[base + 4]) : W[base + 4];
        }
    }
    if (stage == 0)
        for (int i = 0; i < 3; i++)
            g_wb.b[l][i] = pack2(bias1[l * 3 + i], bias1[l * 3 + i]);
}

template <int J>
__device__ __forceinline__ void conv_j(const float (&wf)[16], u64 a[3],
                                       u64 s0, u64 s1, u64 s2, u64 s3, u64 s4) {
#pragma unroll
    for (int i = 0; i < 3; i++) {
        const int k = goff(J, i);
        a[i] = fma2(dup2(wf[k + 0]), s0, a[i]);
        a[i] = fma2(dup2(wf[k + 1]), s1, a[i]);
        a[i] = fma2(dup2(wf[k + 2]), s2, a[i]);
        a[i] = fma2(dup2(wf[k + 3]), s3, a[i]);
        if (J <= i) a[i] = fma2(dup2(wf[k + 4]), s4, a[i]);
    }
}

__device__ __forceinline__ float elu_f(float v) {
    return (v > 0.f) ? v : (__expf(v) - 1.f);
}

// R13 stage-2 conv: two adjacent cols at pair-row p, even words + cmb.
__device__ __forceinline__ void conv2(const float* __restrict__ wl,
                                      const u64* __restrict__ tile,
                                      int pstride, int chstride, int p, int cc,
                                      u64 aA[3], u64 aB[3]) {
#pragma unroll
    for (int j = 0; j < 3; j++) {
        const u64* tj = tile + j * chstride + p * pstride + cc;
        u64 L0 = tj[0], L1 = tj[1], L2 = tj[2], L3 = tj[3];
        const u64* tm = tj + pstride;
        u64 M0 = tm[0], M1 = tm[1], M2 = tm[2], M3 = tm[3];
        u64 o0 = cmb(L0, M0), o1 = cmb(L1, M1), o2 = cmb(L2, M2), o3 = cmb(L3, M3);
        alignas(16) float wf[16];
        ((float4*)wf)[0] = ((const float4*)(wl + j * 16))[0];
        ((float4*)wf)[1] = ((const float4*)(wl + j * 16))[1];
        ((float4*)wf)[2] = ((const float4*)(wl + j * 16))[2];
        ((float4*)wf)[3] = ((const float4*)(wl + j * 16))[3];
        if (j == 0) { conv_j<0>(wf, aA, o0, o1, o2, M0, M1); conv_j<0>(wf, aB, o1, o2, o3, M1, M2); }
        if (j == 1) { conv_j<1>(wf, aA, o0, o1, o2, M0, M1); conv_j<1>(wf, aB, o1, o2, o3, M1, M2); }
        if (j == 2) { conv_j<2>(wf, aA, o0, o1, o2, M0, M1); conv_j<2>(wf, aB, o1, o2, o3, M1, M2); }
    }
}

__global__ __launch_bounds__(NT, 4)
void fused_kernel(const float* __restrict__ x, const float* __restrict__ res,
                  float* __restrict__ out) {
    __shared__ alignas(16) WB2 swb;
    __shared__ u64 xsE[3][XQ][XCOLS];
    __shared__ u64 xsO[3][XO][XCOLS];
    __shared__ u64 hsE[2][3][PS][HCOLS];

    const int tid = threadIdx.x;
    const int b   = blockIdx.z;
    const int gy0 = blockIdx.y * TY;
    const int gx0 = blockIdx.x * TX;

    // ---- weights/bias into SMEM ----
    {
        const u64* src = (const u64*)&g_wb;
        u64* dst = (u64*)&swb;
        const int n = sizeof(WB2) / 8;
        for (int q = tid; q < n; q += NT) dst[q] = src[q];
    }

    // ---- x tile, even pair layout ----
    const float* xb = x + (size_t)b * 3 * 128 * 128;
    for (int q = tid; q < 3 * XQ * XCOLS; q += NT) {
        int j  = q / (XQ * XCOLS);
        int r  = (q / XCOLS) % XQ;
        int cc = q % XCOLS;
        int gy = gy0 + 2 * r - 4;
        int gx = gx0 + cc - 2;
        float lo = 0.f, hi = 0.f;
        if ((unsigned)gx < 128u) {
            const float* col = xb + (size_t)j * 128 * 128 + gx;
            if ((unsigned)gy < 128u)       lo = col[(size_t)gy * 128];
            if ((unsigned)(gy + 1) < 128u) hi = col[(size_t)(gy + 1) * 128];
        }
        xsE[j][r][cc] = pack2(lo, hi);
    }
    __syncthreads();

    // ---- odd-parity x copy: xsO[t] = rows (2t-3, 2t-2) = cmb(E[t], E[t+1]) ----
    for (int q = tid; q < 3 * XO * XCOLS; q += NT) {
        int j  = q / (XO * XCOLS);
        int t  = (q / XCOLS) % XO;
        int cc = q % XCOLS;
        xsO[j][t][cc] = cmb(xsE[j][t][cc], xsE[j][t + 1][cc]);
    }

    // ---- stage-1: one task per thread (tid < 153) ----
    const bool sact = (tid < NS1);
    const int ps0 = sact ? tid / 17 : 0;
    const int pc0 = sact ? tid % 17 : 0;
    const int hcA = 2 * pc0, hcB = hcA + 1;
    const bool cokA = ((unsigned)(gx0 + hcA - 1) < 128u);
    const bool cokB = ((unsigned)(gx0 + hcB - 1) < 128u);
    const bool rlo  = ((unsigned)(gy0 + 2 * ps0 - 2) < 128u);
    const bool rhi  = ((unsigned)(gy0 + 2 * ps0 - 1) < 128u);

    // ---- stage-2: tid < 128 ----
    const bool s2act = (tid < 128);
    const int tcx = tid & 15;
    const int tpy = tid >> 4;

    __syncthreads();   // xsO ready

    // hoist stage-1 even-row words (ky=1 rows), latent-invariant: 9 u64
    u64 Mh[3][3];
#pragma unroll
    for (int j = 0; j < 3; j++) {
        const u64* m = &xsE[j][ps0 + 1][hcA];
        Mh[j][0] = m[0]; Mh[j][1] = m[1]; Mh[j][2] = m[2];
    }

    u64 accA[3], accB[3];
    accA[0] = accA[1] = accA[2] = pack2(0.f, 0.f);
    accB[0] = accB[1] = accB[2] = pack2(0.f, 0.f);

    // stage-1 worker: latent l -> hsE[l&1]; odd taps from xsO, even from regs
    auto do_s1 = [&](int l) {
        if (!sact) return;
        const int buf = l & 1;
        const float* w1l = &swb.w[0][l][0][0];
        u64 aA[3] = {swb.b[l][0], swb.b[l][1], swb.b[l][2]};
        u64 aB[3] = {aA[0], aA[1], aA[2]};
#pragma unroll
        for (int j = 0; j < 3; j++) {
            const u64* to = &xsO[j][ps0][hcA];
            u64 o0 = to[0], o1 = to[1], o2 = to[2], o3 = to[3];
            alignas(16) float wf[16];
            ((float4*)wf)[0] = ((const float4*)(w1l + j * 16))[0];
            ((float4*)wf)[1] = ((const float4*)(w1l + j * 16))[1];
            ((float4*)wf)[2] = ((const float4*)(w1l + j * 16))[2];
            ((float4*)wf)[3] = ((const float4*)(w1l + j * 16))[3];
            if (j == 0) { conv_j<0>(wf, aA, o0, o1, o2, Mh[0][0], Mh[0][1]); conv_j<0>(wf, aB, o1, o2, o3, Mh[0][1], Mh[0][2]); }
            if (j == 1) { conv_j<1>(wf, aA, o0, o1, o2, Mh[1][0], Mh[1][1]); conv_j<1>(wf, aB, o1, o2, o3, Mh[1][1], Mh[1][2]); }
            if (j == 2) { conv_j<2>(wf, aA, o0, o1, o2, Mh[2][0], Mh[2][1]); conv_j<2>(wf, aB, o1, o2, o3, Mh[2][1], Mh[2][2]); }
        }
#pragma unroll
        for (int i = 0; i < 3; i++) {
            float lo, hi;
            unpack2(aA[i], lo, hi);
            lo = (cokA && rlo) ? elu_f(lo) : 0.f;
            hi = (cokA && rhi) ? elu_f(hi) : 0.f;
            hsE[buf][i][ps0][hcA] = pack2(lo, hi);
            unpack2(aB[i], lo, hi);
            lo = (cokB && rlo) ? elu_f(lo) : 0.f;
            hi = (cokB && rhi) ? elu_f(hi) : 0.f;
            hsE[buf][i][ps0][hcB] = pack2(lo, hi);
        }
    };

    // ---- software-pipelined latent loop ----
    do_s1(0);
    __syncthreads();
#pragma unroll 1
    for (int l = 0; l < L_DIM; l++) {
        if (l + 1 < L_DIM) do_s1(l + 1);               // fills hsE[(l+1)&1]
        if (s2act)                                      // reads hsE[l&1]
            conv2(&swb.w[1][l][0][0], &hsE[l & 1][0][0][0], HCOLS, PS * HCOLS,
                  tpy, 2 * tcx, accA, accB);
        __syncthreads();
    }

    // ---- epilogue: mean + gated residual (tid < 128) ----
    if (s2act) {
        const float r = res[0];
        const float g = (r > 0.f) ? r : 0.f;
        const int gy = gy0 + 2 * tpy;
        const int gxA = gx0 + 2 * tcx;
        float* ob = out + (size_t)b * 3 * 128 * 128;
#pragma unroll
        for (int i = 0; i < 3; i++) {
            float lo, hi, xlo, xhi;
            unpack2(accA[i], lo, hi);
            unpack2(xsE[i][tpy + 2][2 * tcx + 2], xlo, xhi);
            ob[(i * 128 + gy) * 128 + gxA]     = lo * (1.f / 16.f) + g * xlo;
            ob[(i * 128 + gy + 1) * 128 + gxA] = hi * (1.f / 16.f) + g * xhi;
            unpack2(accB[i], lo, hi);
            unpack2(xsE[i][tpy + 2][2 * tcx + 3], xlo, xhi);
            ob[(i * 128 + gy) * 128 + gxA + 1]     = lo * (1.f / 16.f) + g * xlo;
            ob[(i * 128 + gy + 1) * 128 + gxA + 1] = hi * (1.f / 16.f) + g * xhi;
        }
    }
}

extern "C" void kernel_launch(void* const* d_in, const int* in_sizes, int n_in,
                              void* d_out, int out_size) {
    const float* x  = (const float*)d_in[0];
    const float* w1 = (const float*)d_in[1];
    const float* c1 = (const float*)d_in[2];
    const float* b1 = (const float*)d_in[3];
    const float* w2 = (const float*)d_in[4];
    const float* c2 = (const float*)d_in[5];
    const float* rs = (const float*)d_in[6];
    (void)in_sizes; (void)n_in; (void)out_size;

    prep_kernel<<<1, 32>>>(w1, c1, b1, w2, c2);

    dim3 grid(128 / TX, 128 / TY, 64);
    fused_kernel<<<grid, NT>>>(x, rs, (float*)d_out);
}

// round 15
// speedup vs baseline: 2.0392x; 1.0226x over previous
#include <cuda_runtime.h>

// ---------------------------------------------------------------------------
// Fused BasicBlockA, round 15 = R14 (131.8us) + column-parity-split tiles.
// R14 audit: all hot-loop LDS.64/STS.64 were stride-2 u64 (16B/lane) ->
// 2-way bank conflicts -> 2x wavefronts. Split every per-latent tile by
// column parity (A=even storage cols, B=odd): each warp access becomes
// unit-stride/contiguous, N=1.
//  - xsOA/xsOB : odd-row-parity x tile, col-parity split (s1 ky0 taps).
//  - hsA/hsB   : h tile, double-buffered, col-parity split.
// Pipeline (s1(l+1) || s2(l)), NT=160, weights scheme: unchanged from R14.
// ---------------------------------------------------------------------------

#define L_DIM 16
#define TX 32
#define TY 16
#define NT 160
#define XQ 10        // xsE pair q = x rel rows (2q-4, 2q-3)
#define XO 9         // xsO pair t = x rel rows (2t-3, 2t-2)
#define PS 9         // h pair p = h rel rows (2p-2, 2p-1)
#define XCOLS 37     // xsE storage col = rel col + 2
#define ACOLS 19     // parity arrays: even cols 0..36 -> 19 (odd padded)
#define HACOLS 18    // h parity arrays: even cols 0..34 -> 18 (odd 17 pad 18)
#define NS1 (PS * 17)  // 153 stage-1 tasks

typedef unsigned long long u64;

struct WB2 {
    float w[2][L_DIM][3][16];  // [stage][latent][j][chunk16]
    u64   b[L_DIM][3];
};
__device__ WB2 g_wb;

__device__ __forceinline__ float softplus_f(float v) {
    return fmaxf(v, 0.f) + log1pf(expf(-fabsf(v)));
}
__device__ __forceinline__ u64 pack2(float lo, float hi) {
    u64 r; asm("mov.b64 %0, {%1, %2};" : "=l"(r) : "f"(lo), "f"(hi)); return r;
}
__device__ __forceinline__ void unpack2(u64 v, float& lo, float& hi) {
    asm("mov.b64 {%0, %1}, %2;" : "=f"(lo), "=f"(hi) : "l"(v));
}
__device__ __forceinline__ u64 fma2(u64 a, u64 b, u64 c) {
    u64 d; asm("fma.rn.f32x2 %0, %1, %2, %3;" : "=l"(d) : "l"(a), "l"(b), "l"(c)); return d;
}
__device__ __forceinline__ u64 dup2(float f) { return pack2(f, f); }
__device__ __forceinline__ u64 cmb(u64 A, u64 B) {   // (A.hi, B.lo)
    float al, ah, bl, bh;
    unpack2(A, al, ah); unpack2(B, bl, bh);
    return pack2(ah, bl);
}

__device__ __host__ __forceinline__ constexpr int goff(int j, int i) {
    constexpr int t[3][3] = {{0, 5, 10}, {0, 4, 9}, {0, 4, 8}};
    return t[j][i];
}

__global__ void prep_kernel(const float* __restrict__ w1, const float* __restrict__ c1,
                            const float* __restrict__ bias1,
                            const float* __restrict__ w2, const float* __restrict__ c2) {
    int t = threadIdx.x;
    if (t >= 2 * L_DIM) return;
    int stage = t >> 4;
    int l = t & 15;
    const float* W = stage ? w2 : w1;
    const float* C = stage ? c2 : c1;
    for (int j = 0; j < 3; j++) {
        float* dst = g_wb.w[stage][l][j];
        for (int k = 0; k < 16; k++) dst[k] = 0.f;
        for (int i = 0; i < 3; i++) {
            int base = ((l * 3 + i) * 3 + j) * 9;
            int k = goff(j, i);
            dst[k + 0] = W[base + 0];
            dst[k + 1] = W[base + 1];
            dst[k + 2] = W[base + 2];
            dst[k + 3] = W[base + 3];
            if (j <= i)
                dst[k + 4] = (j == i) ? softplus_f(C[base + 4]) : W[base + 4];
        }
    }
    if (stage == 0)
        for (int i = 0; i < 3; i++)
            g_wb.b[l][i] = pack2(bias1[l * 3 + i], bias1[l * 3 + i]);
}

template <int J>
__device__ __forceinline__ void conv_j(const float (&wf)[16], u64 a[3],
                                       u64 s0, u64 s1, u64 s2, u64 s3, u64 s4) {
#pragma unroll
    for (int i = 0; i < 3; i++) {
        const int k = goff(J, i);
        a[i] = fma2(dup2(wf[k + 0]), s0, a[i]);
        a[i] = fma2(dup2(wf[k + 1]), s1, a[i]);
        a[i] = fma2(dup2(wf[k + 2]), s2, a[i]);
        a[i] = fma2(dup2(wf[k + 3]), s3, a[i]);
        if (J <= i) a[i] = fma2(dup2(wf[k + 4]), s4, a[i]);
    }
}

__device__ __forceinline__ float elu_f(float v) {
    return (v > 0.f) ? v : (__expf(v) - 1.f);
}

__global__ __launch_bounds__(NT, 4)
void fused_kernel(const float* __restrict__ x, const float* __restrict__ res,
                  float* __restrict__ out) {
    __shared__ alignas(16) WB2 swb;
    __shared__ u64 xsE[3][XQ][XCOLS];
    __shared__ u64 xsOA[3][XO][ACOLS];
    __shared__ u64 xsOB[3][XO][ACOLS];
    __shared__ u64 hsA[2][3][PS][HACOLS];
    __shared__ u64 hsB[2][3][PS][HACOLS];

    const int tid = threadIdx.x;
    const int b   = blockIdx.z;
    const int gy0 = blockIdx.y * TY;
    const int gx0 = blockIdx.x * TX;

    // ---- weights/bias into SMEM ----
    {
        const u64* src = (const u64*)&g_wb;
        u64* dst = (u64*)&swb;
        const int n = sizeof(WB2) / 8;
        for (int q = tid; q < n; q += NT) dst[q] = src[q];
    }

    // ---- x tile, even pair layout ----
    const float* xb = x + (size_t)b * 3 * 128 * 128;
    for (int q = tid; q < 3 * XQ * XCOLS; q += NT) {
        int j  = q / (XQ * XCOLS);
        int r  = (q / XCOLS) % XQ;
        int cc = q % XCOLS;
        int gy = gy0 + 2 * r - 4;
        int gx = gx0 + cc - 2;
        float lo = 0.f, hi = 0.f;
        if ((unsigned)gx < 128u) {
            const float* col = xb + (size_t)j * 128 * 128 + gx;
            if ((unsigned)gy < 128u)       lo = col[(size_t)gy * 128];
            if ((unsigned)(gy + 1) < 128u) hi = col[(size_t)(gy + 1) * 128];
        }
        xsE[j][r][cc] = pack2(lo, hi);
    }
    __syncthreads();

    // ---- odd-row-parity x copy, split by column parity ----
    // xsOA[j][t][k] = rows (2t-3,2t-2) at storage col 2k
    // xsOB[j][t][k] = rows (2t-3,2t-2) at storage col 2k+1
    for (int q = tid; q < 3 * XO * ACOLS; q += NT) {
        int j = q / (XO * ACOLS);
        int t = (q / ACOLS) % XO;
        int k = q % ACOLS;
        xsOA[j][t][k] = cmb(xsE[j][t][2 * k], xsE[j][t + 1][2 * k]);
        if (k < ACOLS - 1)
            xsOB[j][t][k] = cmb(xsE[j][t][2 * k + 1], xsE[j][t + 1][2 * k + 1]);
    }

    // ---- stage-1: one task per thread (tid < 153) ----
    const bool sact = (tid < NS1);
    const int ps0 = sact ? tid / 17 : 0;
    const int pc0 = sact ? tid % 17 : 0;
    const int hcA = 2 * pc0, hcB = hcA + 1;
    const bool cokA = ((unsigned)(gx0 + hcA - 1) < 128u);
    const bool cokB = ((unsigned)(gx0 + hcB - 1) < 128u);
    const bool rlo  = ((unsigned)(gy0 + 2 * ps0 - 2) < 128u);
    const bool rhi  = ((unsigned)(gy0 + 2 * ps0 - 1) < 128u);

    // ---- stage-2: tid < 128 ----
    const bool s2act = (tid < 128);
    const int tcx = tid & 15;
    const int tpy = tid >> 4;

    __syncthreads();   // xsOA/xsOB ready

    // hoist stage-1 even-row words (ky=1 rows), latent-invariant: 9 u64
    u64 Mh[3][3];
#pragma unroll
    for (int j = 0; j < 3; j++) {
        const u64* m = &xsE[j][ps0 + 1][hcA];
        Mh[j][0] = m[0]; Mh[j][1] = m[1]; Mh[j][2] = m[2];
    }

    u64 accA[3], accB[3];
    accA[0] = accA[1] = accA[2] = pack2(0.f, 0.f);
    accB[0] = accB[1] = accB[2] = pack2(0.f, 0.f);

    // stage-1 worker: latent l -> hsA/hsB[l&1]; ky0 taps from parity arrays
    auto do_s1 = [&](int l) {
        if (!sact) return;
        const int buf = l & 1;
        const float* w1l = &swb.w[0][l][0][0];
        u64 aA[3] = {swb.b[l][0], swb.b[l][1], swb.b[l][2]};
        u64 aB[3] = {aA[0], aA[1], aA[2]};
#pragma unroll
        for (int j = 0; j < 3; j++) {
            // storage cols hcA..hcA+3 -> A[pc0], B[pc0], A[pc0+1], B[pc0+1]
            u64 o0 = xsOA[j][ps0][pc0];
            u64 o1 = xsOB[j][ps0][pc0];
            u64 o2 = xsOA[j][ps0][pc0 + 1];
            u64 o3 = xsOB[j][ps0][pc0 + 1];
            alignas(16) float wf[16];
            ((float4*)wf)[0] = ((const float4*)(w1l + j * 16))[0];
            ((float4*)wf)[1] = ((const float4*)(w1l + j * 16))[1];
            ((float4*)wf)[2] = ((const float4*)(w1l + j * 16))[2];
            ((float4*)wf)[3] = ((const float4*)(w1l + j * 16))[3];
            if (j == 0) { conv_j<0>(wf, aA, o0, o1, o2, Mh[0][0], Mh[0][1]); conv_j<0>(wf, aB, o1, o2, o3, Mh[0][1], Mh[0][2]); }
            if (j == 1) { conv_j<1>(wf, aA, o0, o1, o2, Mh[1][0], Mh[1][1]); conv_j<1>(wf, aB, o1, o2, o3, Mh[1][1], Mh[1][2]); }
            if (j == 2) { conv_j<2>(wf, aA, o0, o1, o2, Mh[2][0], Mh[2][1]); conv_j<2>(wf, aB, o1, o2, o3, Mh[2][1], Mh[2][2]); }
        }
#pragma unroll
        for (int i = 0; i < 3; i++) {
            float lo, hi;
            unpack2(aA[i], lo, hi);
            lo = (cokA && rlo) ? elu_f(lo) : 0.f;
            hi = (cokA && rhi) ? elu_f(hi) : 0.f;
            hsA[buf][i][ps0][pc0] = pack2(lo, hi);
            unpack2(aB[i], lo, hi);
            lo = (cokB && rlo) ? elu_f(lo) : 0.f;
            hi = (cokB && rhi) ? elu_f(hi) : 0.f;
            hsB[buf][i][ps0][pc0] = pack2(lo, hi);
        }
    };

    // stage-2 worker: latent l from hsA/hsB[l&1] into acc
    auto do_s2 = [&](int l) {
        const int buf = l & 1;
        const float* w2l = &swb.w[1][l][0][0];
#pragma unroll
        for (int j = 0; j < 3; j++) {
            // L row (pair tpy), M row (pair tpy+1); storage cols 2tcx..2tcx+3
            u64 a0 = hsA[buf][j][tpy][tcx],     b0 = hsB[buf][j][tpy][tcx];
            u64 a1 = hsA[buf][j][tpy][tcx + 1], b1 = hsB[buf][j][tpy][tcx + 1];
            u64 A0 = hsA[buf][j][tpy + 1][tcx],     B0 = hsB[buf][j][tpy + 1][tcx];
            u64 A1 = hsA[buf][j][tpy + 1][tcx + 1], B1 = hsB[buf][j][tpy + 1][tcx + 1];
            u64 o0 = cmb(a0, A0), o1 = cmb(b0, B0), o2 = cmb(a1, A1), o3 = cmb(b1, B1);
            alignas(16) float wf[16];
            ((float4*)wf)[0] = ((const float4*)(w2l + j * 16))[0];
            ((float4*)wf)[1] = ((const float4*)(w2l + j * 16))[1];
            ((float4*)wf)[2] = ((const float4*)(w2l + j * 16))[2];
            ((float4*)wf)[3] = ((const float4*)(w2l + j * 16))[3];
            if (j == 0) { conv_j<0>(wf, accA, o0, o1, o2, A0, B0); conv_j<0>(wf, accB, o1, o2, o3, B0, A1); }
            if (j == 1) { conv_j<1>(wf, accA, o0, o1, o2, A0, B0); conv_j<1>(wf, accB, o1, o2, o3, B0, A1); }
            if (j == 2) { conv_j<2>(wf, accA, o0, o1, o2, A0, B0); conv_j<2>(wf, accB, o1, o2, o3, B0, A1); }
        }
    };

    // ---- software-pipelined latent loop ----
    do_s1(0);
    __syncthreads();
#pragma unroll 1
    for (int l = 0; l < L_DIM; l++) {
        if (l + 1 < L_DIM) do_s1(l + 1);   // fills buffer (l+1)&1
        if (s2act) do_s2(l);               // reads buffer l&1
        __syncthreads();
    }

    // ---- epilogue: mean + gated residual (tid < 128) ----
    if (s2act) {
        const float r = res[0];
        const float g = (r > 0.f) ? r : 0.f;
        const int gy = gy0 + 2 * tpy;
        const int gxA = gx0 + 2 * tcx;
        float* ob = out + (size_t)b * 3 * 128 * 128;
#pragma unroll
        for (int i = 0; i < 3; i++) {
            float lo, hi, xlo, xhi;
            unpack2(accA[i], lo, hi);
            unpack2(xsE[i][tpy + 2][2 * tcx + 2], xlo, xhi);
            ob[(i * 128 + gy) * 128 + gxA]     = lo * (1.f / 16.f) + g * xlo;
            ob[(i * 128 + gy + 1) * 128 + gxA] = hi * (1.f / 16.f) + g * xhi;
            unpack2(accB[i], lo, hi);
            unpack2(xsE[i][tpy + 2][2 * tcx + 3], xlo, xhi);
            ob[(i * 128 + gy) * 128 + gxA + 1]     = lo * (1.f / 16.f) + g * xlo;
            ob[(i * 128 + gy + 1) * 128 + gxA + 1] = hi * (1.f / 16.f) + g * xhi;
        }
    }
}

extern "C" void kernel_launch(void* const* d_in, const int* in_sizes, int n_in,
                              void* d_out, int out_size) {
    const float* x  = (const float*)d_in[0];
    const float* w1 = (const float*)d_in[1];
    const float* c1 = (const float*)d_in[2];
    const float* b1 = (const float*)d_in[3];
    const float* w2 = (const float*)d_in[4];
    const float* c2 = (const float*)d_in[5];
    const float* rs = (const float*)d_in[6];
    (void)in_sizes; (void)n_in; (void)out_size;

    prep_kernel<<<1, 32>>>(w1, c1, b1, w2, c2);

    dim3 grid(128 / TX, 128 / TY, 64);
    fused_kernel<<<grid, NT>>>(x, rs, (float*)d_out);
}

// round 16
// speedup vs baseline: 2.0965x; 1.0281x over previous
#include <cuda_runtime.h>

// ---------------------------------------------------------------------------
// Fused BasicBlockA, round 16 = R15 (128.9us) + latent loop unrolled x2 with
// compile-time buffer selection + hoisted base pointers.
// R15 profile: alu 29.3% ~ addressing recompute (rolled loop, buf=l&1) +
// dup2/cmb movs. This round removes the addressing share.
// Structure unchanged: s1(l+1)||s2(l) pipeline, parity-split tiles, NT=160.
// ---------------------------------------------------------------------------

#define L_DIM 16
#define TX 32
#define TY 16
#define NT 160
#define XQ 10        // xsE pair q = x rel rows (2q-4, 2q-3)
#define XO 9         // xsO pair t = x rel rows (2t-3, 2t-2)
#define PS 9         // h pair p = h rel rows (2p-2, 2p-1)
#define XCOLS 37
#define ACOLS 19
#define HACOLS 18
#define NS1 (PS * 17)  // 153

typedef unsigned long long u64;

struct WB2 {
    float w[2][L_DIM][3][16];
    u64   b[L_DIM][3];
};
__device__ WB2 g_wb;

__device__ __forceinline__ float softplus_f(float v) {
    return fmaxf(v, 0.f) + log1pf(expf(-fabsf(v)));
}
__device__ __forceinline__ u64 pack2(float lo, float hi) {
    u64 r; asm("mov.b64 %0, {%1, %2};" : "=l"(r) : "f"(lo), "f"(hi)); return r;
}
__device__ __forceinline__ void unpack2(u64 v, float& lo, float& hi) {
    asm("mov.b64 {%0, %1}, %2;" : "=f"(lo), "=f"(hi) : "l"(v));
}
__device__ __forceinline__ u64 fma2(u64 a, u64 b, u64 c) {
    u64 d; asm("fma.rn.f32x2 %0, %1, %2, %3;" : "=l"(d) : "l"(a), "l"(b), "l"(c)); return d;
}
__device__ __forceinline__ u64 dup2(float f) { return pack2(f, f); }
__device__ __forceinline__ u64 cmb(u64 A, u64 B) {   // (A.hi, B.lo)
    float al, ah, bl, bh;
    unpack2(A, al, ah); unpack2(B, bl, bh);
    return pack2(ah, bl);
}

__device__ __host__ __forceinline__ constexpr int goff(int j, int i) {
    constexpr int t[3][3] = {{0, 5, 10}, {0, 4, 9}, {0, 4, 8}};
    return t[j][i];
}

__global__ void prep_kernel(const float* __restrict__ w1, const float* __restrict__ c1,
                            const float* __restrict__ bias1,
                            const float* __restrict__ w2, const float* __restrict__ c2) {
    int t = threadIdx.x;
    if (t >= 2 * L_DIM) return;
    int stage = t >> 4;
    int l = t & 15;
    const float* W = stage ? w2 : w1;
    const float* C = stage ? c2 : c1;
    for (int j = 0; j < 3; j++) {
        float* dst = g_wb.w[stage][l][j];
        for (int k = 0; k < 16; k++) dst[k] = 0.f;
        for (int i = 0; i < 3; i++) {
            int base = ((l * 3 + i) * 3 + j) * 9;
            int k = goff(j, i);
            dst[k + 0] = W[base + 0];
            dst[k + 1] = W[base + 1];
            dst[k + 2] = W[base + 2];
            dst[k + 3] = W[base + 3];
            if (j <= i)
                dst[k + 4] = (j == i) ? softplus_f(C[base + 4]) : W[base + 4];
        }
    }
    if (stage == 0)
        for (int i = 0; i < 3; i++)
            g_wb.b[l][i] = pack2(bias1[l * 3 + i], bias1[l * 3 + i]);
}

template <int J>
__device__ __forceinline__ void conv_j(const float (&wf)[16], u64 a[3],
                                       u64 s0, u64 s1, u64 s2, u64 s3, u64 s4) {
#pragma unroll
    for (int i = 0; i < 3; i++) {
        const int k = goff(J, i);
        a[i] = fma2(dup2(wf[k + 0]), s0, a[i]);
        a[i] = fma2(dup2(wf[k + 1]), s1, a[i]);
        a[i] = fma2(dup2(wf[k + 2]), s2, a[i]);
        a[i] = fma2(dup2(wf[k + 3]), s3, a[i]);
        if (J <= i) a[i] = fma2(dup2(wf[k + 4]), s4, a[i]);
    }
}

__device__ __forceinline__ float elu_f(float v) {
    return (v > 0.f) ? v : (__expf(v) - 1.f);
}

__global__ __launch_bounds__(NT, 4)
void fused_kernel(const float* __restrict__ x, const float* __restrict__ res,
                  float* __restrict__ out) {
    __shared__ alignas(16) WB2 swb;
    __shared__ u64 xsE[3][XQ][XCOLS];
    __shared__ u64 xsOA[3][XO][ACOLS];
    __shared__ u64 xsOB[3][XO][ACOLS];
    __shared__ u64 hsA[2][3][PS][HACOLS];
    __shared__ u64 hsB[2][3][PS][HACOLS];

    const int tid = threadIdx.x;
    const int b   = blockIdx.z;
    const int gy0 = blockIdx.y * TY;
    const int gx0 = blockIdx.x * TX;

    // ---- weights/bias into SMEM ----
    {
        const u64* src = (const u64*)&g_wb;
        u64* dst = (u64*)&swb;
        const int n = sizeof(WB2) / 8;
        for (int q = tid; q < n; q += NT) dst[q] = src[q];
    }

    // ---- x tile, even pair layout ----
    const float* xb = x + (size_t)b * 3 * 128 * 128;
    for (int q = tid; q < 3 * XQ * XCOLS; q += NT) {
        int j  = q / (XQ * XCOLS);
        int r  = (q / XCOLS) % XQ;
        int cc = q % XCOLS;
        int gy = gy0 + 2 * r - 4;
        int gx = gx0 + cc - 2;
        float lo = 0.f, hi = 0.f;
        if ((unsigned)gx < 128u) {
            const float* col = xb + (size_t)j * 128 * 128 + gx;
            if ((unsigned)gy < 128u)       lo = col[(size_t)gy * 128];
            if ((unsigned)(gy + 1) < 128u) hi = col[(size_t)(gy + 1) * 128];
        }
        xsE[j][r][cc] = pack2(lo, hi);
    }
    __syncthreads();

    // ---- odd-row-parity x copy, split by column parity ----
    for (int q = tid; q < 3 * XO * ACOLS; q += NT) {
        int j = q / (XO * ACOLS);
        int t = (q / ACOLS) % XO;
        int k = q % ACOLS;
        xsOA[j][t][k] = cmb(xsE[j][t][2 * k], xsE[j][t + 1][2 * k]);
        if (k < ACOLS - 1)
            xsOB[j][t][k] = cmb(xsE[j][t][2 * k + 1], xsE[j][t + 1][2 * k + 1]);
    }

    // ---- stage-1 decode (latent-invariant) ----
    const bool sact = (tid < NS1);
    const int ps0 = sact ? tid / 17 : 0;
    const int pc0 = sact ? tid % 17 : 0;
    const int hcA = 2 * pc0;
    const bool cokA = ((unsigned)(gx0 + hcA - 1) < 128u);
    const bool cokB = ((unsigned)(gx0 + hcA) < 128u);
    const bool rlo  = ((unsigned)(gy0 + 2 * ps0 - 2) < 128u);
    const bool rhi  = ((unsigned)(gy0 + 2 * ps0 - 1) < 128u);

    // ---- stage-2 decode ----
    const bool s2act = (tid < 128);
    const int tcx = tid & 15;
    const int tpy = tid >> 4;

    __syncthreads();   // xsOA/xsOB ready

    // hoist stage-1 even-row words (latent-invariant)
    u64 Mh[3][3];
#pragma unroll
    for (int j = 0; j < 3; j++) {
        const u64* m = &xsE[j][ps0 + 1][hcA];
        Mh[j][0] = m[0]; Mh[j][1] = m[1]; Mh[j][2] = m[2];
    }

    // hoisted base pointers (compile-time offsets from these in the loop)
    // s1 odd-parity sources
    const u64* xoA0 = &xsOA[0][ps0][pc0];
    const u64* xoB0 = &xsOB[0][ps0][pc0];
    // s1 write targets per buffer
    u64* hwA[2] = { &hsA[0][0][ps0][pc0], &hsA[1][0][ps0][pc0] };
    u64* hwB[2] = { &hsB[0][0][ps0][pc0], &hsB[1][0][ps0][pc0] };
    // s2 read bases per buffer (row tpy and tpy+1)
    const u64* rA[2] = { &hsA[0][0][tpy][tcx], &hsA[1][0][tpy][tcx] };
    const u64* rB[2] = { &hsB[0][0][tpy][tcx], &hsB[1][0][tpy][tcx] };

    u64 accA[3], accB[3];
    accA[0] = accA[1] = accA[2] = pack2(0.f, 0.f);
    accB[0] = accB[1] = accB[2] = pack2(0.f, 0.f);

    constexpr int XOJ = XO * ACOLS;      // xsO channel stride (u64)
    constexpr int HJ  = PS * HACOLS;     // hs channel stride (u64)

    // stage-1 worker for latent l into buffer BUF (compile-time)
    auto do_s1 = [&](int l, u64* wA, u64* wB) {
        if (!sact) return;
        const float* w1l = &swb.w[0][l][0][0];
        u64 aA[3] = {swb.b[l][0], swb.b[l][1], swb.b[l][2]};
        u64 aB[3] = {aA[0], aA[1], aA[2]};
#pragma unroll
        for (int j = 0; j < 3; j++) {
            u64 o0 = xoA0[j * XOJ];
            u64 o1 = xoB0[j * XOJ];
            u64 o2 = xoA0[j * XOJ + 1];
            u64 o3 = xoB0[j * XOJ + 1];
            alignas(16) float wf[16];
            ((float4*)wf)[0] = ((const float4*)(w1l + j * 16))[0];
            ((float4*)wf)[1] = ((const float4*)(w1l + j * 16))[1];
            ((float4*)wf)[2] = ((const float4*)(w1l + j * 16))[2];
            ((float4*)wf)[3] = ((const float4*)(w1l + j * 16))[3];
            if (j == 0) { conv_j<0>(wf, aA, o0, o1, o2, Mh[0][0], Mh[0][1]); conv_j<0>(wf, aB, o1, o2, o3, Mh[0][1], Mh[0][2]); }
            if (j == 1) { conv_j<1>(wf, aA, o0, o1, o2, Mh[1][0], Mh[1][1]); conv_j<1>(wf, aB, o1, o2, o3, Mh[1][1], Mh[1][2]); }
            if (j == 2) { conv_j<2>(wf, aA, o0, o1, o2, Mh[2][0], Mh[2][1]); conv_j<2>(wf, aB, o1, o2, o3, Mh[2][1], Mh[2][2]); }
        }
#pragma unroll
        for (int i = 0; i < 3; i++) {
            float lo, hi;
            unpack2(aA[i], lo, hi);
            lo = (cokA && rlo) ? elu_f(lo) : 0.f;
            hi = (cokA && rhi) ? elu_f(hi) : 0.f;
            wA[i * HJ] = pack2(lo, hi);
            unpack2(aB[i], lo, hi);
            lo = (cokB && rlo) ? elu_f(lo) : 0.f;
            hi = (cokB && rhi) ? elu_f(hi) : 0.f;
            wB[i * HJ] = pack2(lo, hi);
        }
    };

    // stage-2 worker for latent l from buffer bases rdA/rdB
    auto do_s2 = [&](int l, const u64* rdA, const u64* rdB) {
        const float* w2l = &swb.w[1][l][0][0];
#pragma unroll
        for (int j = 0; j < 3; j++) {
            const u64* pa = rdA + j * HJ;
            const u64* pb = rdB + j * HJ;
            u64 a0 = pa[0], b0 = pb[0], a1 = pa[1], b1 = pb[1];
            u64 A0 = pa[HACOLS], B0 = pb[HACOLS], A1 = pa[HACOLS + 1], B1 = pb[HACOLS + 1];
            u64 o0 = cmb(a0, A0), o1 = cmb(b0, B0), o2 = cmb(a1, A1), o3 = cmb(b1, B1);
            alignas(16) float wf[16];
            ((float4*)wf)[0] = ((const float4*)(w2l + j * 16))[0];
            ((float4*)wf)[1] = ((const float4*)(w2l + j * 16))[1];
            ((float4*)wf)[2] = ((const float4*)(w2l + j * 16))[2];
            ((float4*)wf)[3] = ((const float4*)(w2l + j * 16))[3];
            if (j == 0) { conv_j<0>(wf, accA, o0, o1, o2, A0, B0); conv_j<0>(wf, accB, o1, o2, o3, B0, A1); }
            if (j == 1) { conv_j<1>(wf, accA, o0, o1, o2, A0, B0); conv_j<1>(wf, accB, o1, o2, o3, B0, A1); }
            if (j == 2) { conv_j<2>(wf, accA, o0, o1, o2, A0, B0); conv_j<2>(wf, accB, o1, o2, o3, B0, A1); }
        }
    };

    // ---- software-pipelined latent loop, unrolled x2 (buf compile-time) ----
    do_s1(0, hwA[0], hwB[0]);
    __syncthreads();
#pragma unroll 1
    for (int l = 0; l < L_DIM; l += 2) {
        // iteration A: s1(l+1)->buf1, s2(l)<-buf0
        do_s1(l + 1, hwA[1], hwB[1]);
        if (s2act) do_s2(l, rA[0], rB[0]);
        __syncthreads();
        // iteration B: s1(l+2)->buf0 (skip when l+2==L_DIM), s2(l+1)<-buf1
        if (l + 2 < L_DIM) do_s1(l + 2, hwA[0], hwB[0]);
        if (s2act) do_s2(l + 1, rA[1], rB[1]);
        __syncthreads();
    }

    // ---- epilogue: mean + gated residual (tid < 128) ----
    if (s2act) {
        const float r = res[0];
        const float g = (r > 0.f) ? r : 0.f;
        const int gy = gy0 + 2 * tpy;
        const int gxA = gx0 + 2 * tcx;
        float* ob = out + (size_t)b * 3 * 128 * 128;
#pragma unroll
        for (int i = 0; i < 3; i++) {
            float lo, hi, xlo, xhi;
            unpack2(accA[i], lo, hi);
            unpack2(xsE[i][tpy + 2][2 * tcx + 2], xlo, xhi);
            ob[(i * 128 + gy) * 128 + gxA]     = lo * (1.f / 16.f) + g * xlo;
            ob[(i * 128 + gy + 1) * 128 + gxA] = hi * (1.f / 16.f) + g * xhi;
            unpack2(accB[i], lo, hi);
            unpack2(xsE[i][tpy + 2][2 * tcx + 3], xlo, xhi);
            ob[(i * 128 + gy) * 128 + gxA + 1]     = lo * (1.f / 16.f) + g * xlo;
            ob[(i * 128 + gy + 1) * 128 + gxA + 1] = hi * (1.f / 16.f) + g * xhi;
        }
    }
}

extern "C" void kernel_launch(void* const* d_in, const int* in_sizes, int n_in,
                              void* d_out, int out_size) {
    const float* x  = (const float*)d_in[0];
    const float* w1 = (const float*)d_in[1];
    const float* c1 = (const float*)d_in[2];
    const float* b1 = (const float*)d_in[3];
    const float* w2 = (const float*)d_in[4];
    const float* c2 = (const float*)d_in[5];
    const float* rs = (const float*)d_in[6];
    (void)in_sizes; (void)n_in; (void)out_size;

    prep_kernel<<<1, 32>>>(w1, c1, b1, w2, c2);

    dim3 grid(128 / TX, 128 / TY, 64);
    fused_kernel<<<grid, NT>>>(x, rs, (float*)d_out);
}